// round 10
// baseline (speedup 1.0000x reference)
#include <cuda_runtime.h>
#include <cuda_bf16.h>
#include <cstdint>

// ---------------------------------------------------------------------------
// 2-layer LSTM: B=64, T=512, D=H=1024.  HMMA (mma.sync) path — harness ptx
// target sm_103 rejects tcgen05.
// R10: mega-kernel for layer 0: warps 0-7 = R7 recurrence (named barriers),
// warps 8-11 = GEMM worker computing xg0 (chunk-gated producer for the
// recurrence) and then xg1 (gated on recurrence progress). Both input GEMMs
// ride inside the recurrence's idle tensor/latency slack.
// ---------------------------------------------------------------------------

#define B_DIM 64
#define T_DIM 512
#define H_DIM 1024
#define G_DIM 4096
#define M_TOT (B_DIM * T_DIM)   // 32768
#define NCTA 128

// -------------------- device scratch (no allocs allowed) -------------------
__device__ __nv_bfloat16 g_Ahi[(size_t)M_TOT * H_DIM];   // X split, then out0 split
__device__ __nv_bfloat16 g_Alo[(size_t)M_TOT * H_DIM];
__device__ float         g_xg [(size_t)M_TOT * G_DIM];   // layer-0 gate pre-acts
__device__ float         g_xg2[(size_t)M_TOT * G_DIM];   // layer-1 gate pre-acts
__device__ __nv_bfloat16 g_Whi[(size_t)4 * G_DIM * H_DIM];  // Wih0,Whh0,Wih1,Whh1
__device__ __nv_bfloat16 g_Wlo[(size_t)4 * G_DIM * H_DIM];
__device__ float         g_c[B_DIM * H_DIM];
__device__ float         g_h[B_DIM * H_DIM];
__device__ __nv_bfloat16 g_hhi[2][B_DIM * H_DIM];        // double-buffered h split
__device__ __nv_bfloat16 g_hlo[2][B_DIM * H_DIM];
__device__ volatile unsigned g_bar[2];      // recurrence step counters (per layer)
__device__ volatile unsigned g_g0cnt[8];    // xg0 chunk completion (CTAs done)

extern __shared__ char smem_raw[];

// -------------------- PTX helpers ------------------------------------------
__device__ __forceinline__ void mma_bf16(float (&d)[4], const uint32_t (&a)[4],
                                         uint32_t b0, uint32_t b1) {
    asm volatile(
        "mma.sync.aligned.m16n8k16.row.col.f32.bf16.bf16.f32 "
        "{%0,%1,%2,%3}, {%4,%5,%6,%7}, {%8,%9}, {%0,%1,%2,%3};\n"
        : "+f"(d[0]), "+f"(d[1]), "+f"(d[2]), "+f"(d[3])
        : "r"(a[0]), "r"(a[1]), "r"(a[2]), "r"(a[3]), "r"(b0), "r"(b1));
}
__device__ __forceinline__ void ldsm4(uint32_t (&r)[4], const __nv_bfloat16* p) {
    uint32_t a = (uint32_t)__cvta_generic_to_shared(p);
    asm volatile("ldmatrix.sync.aligned.m8n8.x4.shared.b16 {%0,%1,%2,%3}, [%4];"
                 : "=r"(r[0]), "=r"(r[1]), "=r"(r[2]), "=r"(r[3]) : "r"(a));
}
__device__ __forceinline__ void cpasync16(uint32_t dst, const void* src) {
    asm volatile("cp.async.cg.shared.global [%0], [%1], 16;" :: "r"(dst), "l"(src));
}
__device__ __forceinline__ void cp_commit() {
    asm volatile("cp.async.commit_group;");
}
template <int N>
__device__ __forceinline__ void cp_wait() {
    asm volatile("cp.async.wait_group %0;" :: "n"(N));
}
__device__ __forceinline__ void barn(int id, int cnt) {
    asm volatile("bar.sync %0, %1;" :: "r"(id), "r"(cnt) : "memory");
}

// -------------------- split fp32 -> bf16 hi/lo ------------------------------
__global__ void split_kernel(const float* __restrict__ src, int sel, int n) {
    __nv_bfloat16 *hi, *lo;
    if (sel == 0) { hi = g_Ahi; lo = g_Alo; }
    else {
        size_t o = (size_t)(sel - 1) * G_DIM * H_DIM;
        hi = g_Whi + o; lo = g_Wlo + o;
    }
    const size_t stride = (size_t)gridDim.x * blockDim.x * 4;
    for (size_t i = ((size_t)blockIdx.x * blockDim.x + threadIdx.x) * 4;
         i < (size_t)n; i += stride) {
        float4 v = *(const float4*)(src + i);
        __nv_bfloat16 h0 = __float2bfloat16(v.x);
        __nv_bfloat16 h1 = __float2bfloat16(v.y);
        __nv_bfloat16 h2 = __float2bfloat16(v.z);
        __nv_bfloat16 h3 = __float2bfloat16(v.w);
        __nv_bfloat16 l0 = __float2bfloat16(v.x - __bfloat162float(h0));
        __nv_bfloat16 l1 = __float2bfloat16(v.y - __bfloat162float(h1));
        __nv_bfloat16 l2 = __float2bfloat16(v.z - __bfloat162float(h2));
        __nv_bfloat16 l3 = __float2bfloat16(v.w - __bfloat162float(h3));
        __nv_bfloat162* ph = reinterpret_cast<__nv_bfloat162*>(hi + i);
        __nv_bfloat162* pl = reinterpret_cast<__nv_bfloat162*>(lo + i);
        ph[0] = __halves2bfloat162(h0, h1);
        ph[1] = __halves2bfloat162(h2, h3);
        pl[0] = __halves2bfloat162(l0, l1);
        pl[1] = __halves2bfloat162(l2, l3);
    }
}

__global__ void zero_state_kernel() {
    int i = blockIdx.x * blockDim.x + threadIdx.x;
    if (i < 2) *((unsigned*)&g_bar[i]) = 0u;
    if (i >= 2 && i < 10) *((unsigned*)&g_g0cnt[i - 2]) = 0u;
    if (i < B_DIM * H_DIM) {
        g_h[i] = 0.f; g_c[i] = 0.f;
        __nv_bfloat16 z = __float2bfloat16(0.f);
        g_hhi[0][i] = z; g_hhi[1][i] = z;
        g_hlo[0][i] = z; g_hlo[1][i] = z;
    }
}

__global__ void copy_state_kernel(float* __restrict__ dh, float* __restrict__ dc) {
    int i = blockIdx.x * blockDim.x + threadIdx.x;
    if (i < B_DIM * H_DIM) { dh[i] = g_h[i]; dc[i] = g_c[i]; }
}

// -------------------- mega kernel -------------------------------------------
// smem layout (dynamic):
//   [0)                recurrence: W slice hi+lo   32*WS*2 elems * 2B = 132096
//   [132096)           H pipeline: NSTAGE*2*STG_E*2B            = 40960
//   [173056)           GEMM worker: Ah,Al,Bh,Bl  [2][64*40] each = 40960
#define WS 1032
#define SA 40
#define STG_E (64 * SA)
#define NSTAGE 4
#define SMEM_REC (32 * WS * 2 * 2 + NSTAGE * 2 * STG_E * 2)   // 173056
#define SMEM_TOT (SMEM_REC + 4 * 2 * 2560 * 2)                // 214016

__global__ __launch_bounds__(384) void lstm_mega_kernel(
    int wsel_rec, int layer, float* __restrict__ out,
    const float* __restrict__ bi0, const float* __restrict__ bh0,
    const float* __restrict__ bi1, const float* __restrict__ bh1,
    int enable_gemm) {
    constexpr int BK = 32, K = H_DIM, NKB = K / BK;
    const int nblk = blockIdx.x;                 // 0..127
    const int tid = threadIdx.x;

    // =================== GEMM worker role (warps 8-11) =====================
    if (tid >= 256) {
        if (enable_gemm) {
            const int tid2 = tid - 256;
            const int lane2 = tid2 & 31, wid2 = tid2 >> 5;
            const int wr = wid2 & 1, wc = wid2 >> 1;
            const int gidg = lane2 >> 2, tgg = lane2 & 3;
            const int lofs = (lane2 & 15) * 40 + (lane2 >> 4) * 8;
            __nv_bfloat16* sG0 = (__nv_bfloat16*)(smem_raw + SMEM_REC);
            const uint32_t sgb = (uint32_t)__cvta_generic_to_shared(sG0);
            // loader: 128 threads, per tile-array 2 uint4 each
            const int lrow = tid2 >> 1, lv = tid2 & 1;
            const uint32_t s_o0 = (uint32_t)(lrow * 40 + lv * 8) * 2;
            const uint32_t s_o1 = (uint32_t)(lrow * 40 + (lv + 2) * 8) * 2;
            const size_t g_o0 = (size_t)lv * 8, g_o1 = (size_t)(lv + 2) * 8;

            auto do_tile = [&](const __nv_bfloat16* __restrict__ Bh,
                               const __nv_bfloat16* __restrict__ Bl,
                               float* __restrict__ xout,
                               const float* __restrict__ c1,
                               const float* __restrict__ c2,
                               int m0, int n0) {
                float ac[2][4][4];
#pragma unroll
                for (int i = 0; i < 2; ++i)
#pragma unroll
                    for (int j = 0; j < 4; ++j)
#pragma unroll
                        for (int q = 0; q < 4; ++q) ac[i][j][q] = 0.f;
                const size_t arow = (size_t)(m0 + lrow) * H_DIM;
                const size_t brow = (size_t)(n0 + lrow) * H_DIM;

                auto ld = [&](int kb, int buf) {
                    const uint32_t bb = sgb + (uint32_t)buf * 5120;
                    const size_t ka = arow + (size_t)kb * 32;
                    const size_t kn = brow + (size_t)kb * 32;
                    cpasync16(bb + s_o0,          g_Ahi + ka + g_o0);
                    cpasync16(bb + s_o1,          g_Ahi + ka + g_o1);
                    cpasync16(bb + 10240 + s_o0,  g_Alo + ka + g_o0);
                    cpasync16(bb + 10240 + s_o1,  g_Alo + ka + g_o1);
                    cpasync16(bb + 20480 + s_o0,  Bh + kn + g_o0);
                    cpasync16(bb + 20480 + s_o1,  Bh + kn + g_o1);
                    cpasync16(bb + 30720 + s_o0,  Bl + kn + g_o0);
                    cpasync16(bb + 30720 + s_o1,  Bl + kn + g_o1);
                };

                ld(0, 0);
                cp_commit();
                for (int kb = 0; kb < 32; ++kb) {
                    if (kb + 1 < 32) { ld(kb + 1, (kb + 1) & 1); cp_commit(); cp_wait<1>(); }
                    else             { cp_wait<0>(); }
                    barn(2, 128);
                    const int bo = (kb & 1) * 2560;
                    const __nv_bfloat16* pAh = sG0 + bo;
                    const __nv_bfloat16* pAl = sG0 + 5120 + bo;
                    const __nv_bfloat16* pBh = sG0 + 10240 + bo;
                    const __nv_bfloat16* pBl = sG0 + 15360 + bo;
#pragma unroll
                    for (int ks = 0; ks < 2; ++ks) {
                        const int k16 = ks * 16;
                        uint32_t ah[2][4], al[2][4], bh[2][4], bl[2][4];
                        ldsm4(ah[0], pAh + (wr * 32) * 40 + k16 + lofs);
                        ldsm4(ah[1], pAh + (wr * 32 + 16) * 40 + k16 + lofs);
                        ldsm4(al[0], pAl + (wr * 32) * 40 + k16 + lofs);
                        ldsm4(al[1], pAl + (wr * 32 + 16) * 40 + k16 + lofs);
                        ldsm4(bh[0], pBh + (wc * 32) * 40 + k16 + lofs);
                        ldsm4(bh[1], pBh + (wc * 32 + 16) * 40 + k16 + lofs);
                        ldsm4(bl[0], pBl + (wc * 32) * 40 + k16 + lofs);
                        ldsm4(bl[1], pBl + (wc * 32 + 16) * 40 + k16 + lofs);
#pragma unroll
                        for (int im = 0; im < 2; ++im)
#pragma unroll
                            for (int j = 0; j < 4; ++j) {
                                const uint32_t* WH = bh[j >> 1];
                                const uint32_t* WL = bl[j >> 1];
                                const int e = j & 1;
                                mma_bf16(ac[im][j], ah[im], WH[e], WH[e + 2]);
                                mma_bf16(ac[im][j], ah[im], WL[e], WL[e + 2]);
                                mma_bf16(ac[im][j], al[im], WH[e], WH[e + 2]);
                            }
                    }
                }
                // epilogue with bias
#pragma unroll
                for (int im = 0; im < 2; ++im)
#pragma unroll
                    for (int j = 0; j < 4; ++j) {
                        const int row = m0 + wr * 32 + im * 16 + gidg;
                        const int col = n0 + wc * 32 + j * 8 + tgg * 2;
                        const float q0 = c1[col] + c2[col];
                        const float q1 = c1[col + 1] + c2[col + 1];
                        float2 v0 = make_float2(ac[im][j][0] + q0, ac[im][j][1] + q1);
                        float2 v1 = make_float2(ac[im][j][2] + q0, ac[im][j][3] + q1);
                        *(float2*)&xout[(size_t)row * G_DIM + col] = v0;
                        *(float2*)&xout[(size_t)(row + 8) * G_DIM + col] = v1;
                    }
            };

            const __nv_bfloat16* W0h = g_Whi;                              // slot 0
            const __nv_bfloat16* W0l = g_Wlo;
            const __nv_bfloat16* W2h = g_Whi + (size_t)2 * G_DIM * H_DIM;  // slot 2
            const __nv_bfloat16* W2l = g_Wlo + (size_t)2 * G_DIM * H_DIM;

            // pass 0: xg0 (producer for the recurrence), chunked by t
            for (int tc = 0; tc < 8; ++tc) {
                for (int j = 0; j < 32; ++j) {
                    const int idx = nblk + 128 * j;        // 0..4095
                    const int b = idx >> 6, nt = idx & 63;
                    do_tile(W0h, W0l, g_xg, bi0, bh0, b * 512 + tc * 64, nt * 64);
                }
                __threadfence();
                barn(2, 128);
                if (tid2 == 0) atomicAdd((unsigned*)&g_g0cnt[tc], 1u);
            }
            // pass 1: xg1, gated on recurrence progress
            for (int tc = 0; tc < 8; ++tc) {
                const unsigned need = (unsigned)(tc + 1) * 8192u;
                while (g_bar[0] < need) { __nanosleep(256); }
                __threadfence();
                for (int j = 0; j < 32; ++j) {
                    const int idx = nblk + 128 * j;
                    const int b = idx >> 6, nt = idx & 63;
                    do_tile(W2h, W2l, g_xg2, bi1, bh1, b * 512 + tc * 64, nt * 64);
                }
            }
        }
        return;
    }

    // =================== recurrence role (warps 0-7, R7 code) ==============
    __nv_bfloat16* sWh = (__nv_bfloat16*)smem_raw;                    // 32*WS
    __nv_bfloat16* sWl = sWh + 32 * WS;                               // 32*WS
    __nv_bfloat16* sH  = sWl + 32 * WS;

    const int lane = tid & 31, wid = tid >> 5;
    const int wr = wid & 1;                      // m strip (2 x 32)
    const int wc = wid >> 1;                     // n strip (4 x 8)
    const int gid = lane >> 2, tg = lane & 3;

    const int aofs = (lane & 15) * SA + (lane >> 4) * 8;
    const int wofs = (wc * 8 + (lane & 7)) * WS + (lane >> 3) * 8;

    const size_t woff = (size_t)wsel_rec * G_DIM * H_DIM;
    const float* __restrict__ xgsrc = layer ? g_xg2 : g_xg;

    // ---- load W_hh slice into smem (once) ----
    {
        const int wrow = tid >> 3, wvec = tid & 7;
        const int gsel = wrow >> 3, r8 = wrow & 7;
        const size_t grow = woff + (size_t)(gsel * H_DIM + nblk * 8 + r8) * K;
#pragma unroll 4
        for (int k = wvec * 4; k < K; k += 32) {
            *(uint2*)&sWh[wrow * WS + k] = *(const uint2*)(g_Whi + grow + k);
            *(uint2*)&sWl[wrow * WS + k] = *(const uint2*)(g_Wlo + grow + k);
        }
    }
    barn(1, 256);

    float creg[2] = {0.f, 0.f};

    const int hrow = tid >> 2, hvec = tid & 3;
    const uint32_t sH_base = (uint32_t)__cvta_generic_to_shared(sH);
    const uint32_t dst_lane = (uint32_t)(hrow * SA + hvec * 8) * 2;
    const size_t gsrc_lane = (size_t)hrow * K + hvec * 8;

    const int pb0 = tid >> 3, phc = tid & 7;
    const int colg = nblk * 8 + phc;

    for (int t = 0; t < T_DIM; ++t) {
        // ---- gate on xg0 chunk availability (layer 0 only) ----
        if (enable_gemm && (t & 63) == 0) {
            if (tid == 0) { while (g_g0cnt[t >> 6] < 128u) { } }
            barn(1, 256);
            __threadfence();
        }

        const int rbuf = t & 1;
        const __nv_bfloat16* __restrict__ Hh = g_hhi[rbuf];
        const __nv_bfloat16* __restrict__ Hl = g_hlo[rbuf];

        // ---- prefetch xg ----
        float px[2][4];
#pragma unroll
        for (int half = 0; half < 2; ++half) {
            const int b = pb0 + half * 32;
            const float* xp = xgsrc + ((size_t)b * T_DIM + t) * G_DIM + colg;
            px[half][0] = xp[0];
            px[half][1] = xp[H_DIM];
            px[half][2] = xp[2 * H_DIM];
            px[half][3] = xp[3 * H_DIM];
        }

        // ---- prologue stages ----
#pragma unroll
        for (int s = 0; s < NSTAGE - 1; ++s) {
            const uint32_t d = sH_base + (uint32_t)(s * 2 * STG_E) * 2 + dst_lane;
            cpasync16(d, Hh + gsrc_lane + s * BK);
            cpasync16(d + STG_E * 2, Hl + gsrc_lane + s * BK);
            cp_commit();
        }

        float ahh[2][4], ahl[2][4], alh[2][4];
#pragma unroll
        for (int i = 0; i < 2; i++)
#pragma unroll
            for (int q = 0; q < 4; q++) { ahh[i][q] = 0.f; ahl[i][q] = 0.f; alh[i][q] = 0.f; }

#pragma unroll 4
        for (int kb = 0; kb < NKB; ++kb) {
            cp_wait<2>();
            barn(1, 256);
            if (kb + NSTAGE - 1 < NKB) {
                const int s = kb + NSTAGE - 1;
                const uint32_t d = sH_base + (uint32_t)((s & 3) * 2 * STG_E) * 2 + dst_lane;
                cpasync16(d, Hh + gsrc_lane + s * BK);
                cpasync16(d + STG_E * 2, Hl + gsrc_lane + s * BK);
            }
            cp_commit();

            const int slot = kb & 3;
            const __nv_bfloat16* sHh_s = sH + slot * 2 * STG_E;
            const __nv_bfloat16* sHl_s = sHh_s + STG_E;

            uint32_t tWh[4], tWl[4];
            ldsm4(tWh, &sWh[wofs + kb * BK]);
            ldsm4(tWl, &sWl[wofs + kb * BK]);
#pragma unroll
            for (int ks = 0; ks < 2; ++ks) {
                const int k16 = ks * 16;
                uint32_t ah[2][4], al[2][4];
#pragma unroll
                for (int im = 0; im < 2; ++im) {
                    const int mrow = wr * 32 + im * 16;
                    ldsm4(ah[im], &sHh_s[mrow * SA + k16 + aofs]);
                    ldsm4(al[im], &sHl_s[mrow * SA + k16 + aofs]);
                }
#pragma unroll
                for (int im = 0; im < 2; ++im) {
                    mma_bf16(ahh[im], ah[im], tWh[ks * 2], tWh[ks * 2 + 1]);
                    mma_bf16(ahl[im], ah[im], tWl[ks * 2], tWl[ks * 2 + 1]);
                    mma_bf16(alh[im], al[im], tWh[ks * 2], tWh[ks * 2 + 1]);
                }
            }
        }

        // gates -> shared (reuse H stage 0 region after pipeline drained)
        float* sG = (float*)sH;
        barn(1, 256);
#pragma unroll
        for (int im = 0; im < 2; ++im) {
            const int m = wr * 32 + im * 16 + gid;
            const int c = wc * 8 + tg * 2;
            sG[m * 33 + c]     = ahh[im][0] + ahl[im][0] + alh[im][0];
            sG[m * 33 + c + 1] = ahh[im][1] + ahl[im][1] + alh[im][1];
            sG[(m + 8) * 33 + c]     = ahh[im][2] + ahl[im][2] + alh[im][2];
            sG[(m + 8) * 33 + c + 1] = ahh[im][3] + ahl[im][3] + alh[im][3];
        }
        barn(1, 256);

        // pointwise LSTM update; c in registers
        const int wb = rbuf ^ 1;
#pragma unroll
        for (int half = 0; half < 2; ++half) {
            const int b = pb0 + half * 32;
            const float vi = sG[b * 33 + phc]      + px[half][0];
            const float vf = sG[b * 33 + 8 + phc]  + px[half][1];
            const float vg = sG[b * 33 + 16 + phc] + px[half][2];
            const float vo = sG[b * 33 + 24 + phc] + px[half][3];
            const float ii = 1.f / (1.f + __expf(-vi));
            const float ff = 1.f / (1.f + __expf(-vf));
            const float gg = tanhf(vg);
            const float oo = 1.f / (1.f + __expf(-vo));
            const float cn = ff * creg[half] + ii * gg;
            creg[half] = cn;
            const float hn = oo * tanhf(cn);
            const __nv_bfloat16 hi = __float2bfloat16(hn);
            const __nv_bfloat16 lo = __float2bfloat16(hn - __bfloat162float(hi));
            const int cidx = b * H_DIM + colg;
            g_hhi[wb][cidx] = hi;
            g_hlo[wb][cidx] = lo;
            const size_t ooff = ((size_t)b * T_DIM + t) * H_DIM + colg;
            if (layer == 0) { g_Ahi[ooff] = hi; g_Alo[ooff] = lo; }
            else            { out[ooff] = hn; }
            if (t == T_DIM - 1) { g_h[cidx] = hn; g_c[cidx] = cn; }
        }

        // ---- grid-wide barrier (publishes h + out0 rows) ----
        __threadfence();
        barn(1, 256);
        if (tid == 0) {
            atomicAdd((unsigned*)&g_bar[layer], 1u);
            const unsigned target = (unsigned)(t + 1) * (unsigned)NCTA;
            while (g_bar[layer] < target) { }
            __threadfence();
        }
        barn(1, 256);
    }
}

// -------------------- host entry -------------------------------------------
extern "C" void kernel_launch(void* const* d_in, const int* in_sizes, int n_in,
                              void* d_out, int out_size) {
    if (n_in < 9) return;
    const float* X    = (const float*)d_in[0];
    const float* Wih0 = (const float*)d_in[1];
    const float* bih0 = (const float*)d_in[2];
    const float* Whh0 = (const float*)d_in[3];
    const float* bhh0 = (const float*)d_in[4];
    const float* Wih1 = (const float*)d_in[5];
    const float* bih1 = (const float*)d_in[6];
    const float* Whh1 = (const float*)d_in[7];
    const float* bhh1 = (const float*)d_in[8];
    float* out = (float*)d_out;

    cudaFuncSetAttribute(lstm_mega_kernel,
                         cudaFuncAttributeMaxDynamicSharedMemorySize, SMEM_TOT);

    const size_t OUT1 = (size_t)M_TOT * H_DIM;
    const size_t BH   = (size_t)B_DIM * H_DIM;
    const bool write_states = (size_t)out_size >= OUT1 + 4 * BH;

    // splits: slot0=Wih0, slot1=Whh0, slot2=Wih1, slot3=Whh1
    split_kernel<<<1184, 256>>>(X,    0, M_TOT * H_DIM);
    split_kernel<<<1184, 256>>>(Wih0, 1, G_DIM * H_DIM);
    split_kernel<<<1184, 256>>>(Whh0, 2, G_DIM * H_DIM);
    split_kernel<<<1184, 256>>>(Wih1, 3, G_DIM * H_DIM);
    split_kernel<<<1184, 256>>>(Whh1, 4, G_DIM * H_DIM);

    // layer 0: recurrence + embedded GEMM0/GEMM1
    zero_state_kernel<<<256, 256>>>();
    lstm_mega_kernel<<<NCTA, 384, SMEM_TOT>>>(1, 0, out,
                                              bih0, bhh0, bih1, bhh1, 1);
    if (write_states)
        copy_state_kernel<<<256, 256>>>(out + OUT1, out + OUT1 + 2 * BH);

    // layer 1: recurrence only (xg1 already computed)
    zero_state_kernel<<<256, 256>>>();
    lstm_mega_kernel<<<NCTA, 384, SMEM_TOT>>>(3, 1, out,
                                              bih0, bhh0, bih1, bhh1, 0);
    if (write_states)
        copy_state_kernel<<<256, 256>>>(out + OUT1 + BH, out + OUT1 + 3 * BH);
}